// round 7
// baseline (speedup 1.0000x reference)
#include <cuda_runtime.h>
#include <cuda_fp16.h>
#include <math.h>

#define NN 50000
#define NE 1200000
#define NG 128
#define NBLK 49            // ceil(NN/1024)
#define ADJ_BLKS ((NE + 255) / 256)
#define T0_BLKS  ((NN + 7) / 8)        // warp-per-node, 8 nodes/block
#define EPSF 1e-7f
#define MAXNORM (1.0f - 1e-5f)
#define ACLAMP 6.1030338f  // arctanh(1 - 1e-5)

// ---------------- scratch (static device globals; no allocation) -------------
__device__ int     g_flagE;
__device__ int     g_flagB;
__device__ int     g_deg[NN];
__device__ int     g_off[NN];
__device__ int     g_cur[NN];
__device__ int     g_adj[NE];
__device__ int     g_bsum[64];
__device__ int     g_gstart[NG + 1];
__device__ float   g_pool[NG * 64];
__device__ __half2 g_tha[NN * 32];   // node features A (stride 16 or 32 half2)
__device__ __half2 g_thb[NN * 32];   // node features B

__device__ __forceinline__ int load_idx(const void* p, int i, int flag64) {
    return flag64 ? (int)((const long long*)p)[i] : ((const int*)p)[i];
}

// ---------------- zero + dtype detection (block 0) ---------------------------
__global__ void zero_kernel(const int* __restrict__ ei, const int* __restrict__ ba) {
    int i = blockIdx.x * blockDim.x + threadIdx.x;
    if (i < NN)      g_deg[i]  = 0;
    if (i < NG * 64) g_pool[i] = 0.0f;
    if (blockIdx.x == 0) {
        __shared__ int nzE, nzB;
        if (threadIdx.x == 0) { nzE = 0; nzB = 0; }
        __syncthreads();
        for (int w = NE + 1 + 2 * threadIdx.x; w < NE + 2048; w += 2 * blockDim.x)
            if (ei[w] != 0) atomicOr(&nzE, 1);
        for (int w = 48001 + 2 * threadIdx.x; w < 50000; w += 2 * blockDim.x)
            if (ba[w] != 0) atomicOr(&nzB, 1);
        __syncthreads();
        if (threadIdx.x == 0) { g_flagE = (nzE == 0); g_flagB = (nzB == 0); }
    }
}

__global__ void deg_kernel(const void* __restrict__ ei) {
    int e = blockIdx.x * blockDim.x + threadIdx.x;
    if (e >= NE) return;
    int dst = load_idx(ei, NE + e, g_flagE);
    atomicAdd(&g_deg[dst], 1);
}

// ---- scan phase 1: 49 blocks x 1024, per-block inclusive scan ---------------
__global__ void scan1_kernel() {
    int i = blockIdx.x * 1024 + threadIdx.x;
    int lane = threadIdx.x & 31, wid = threadIdx.x >> 5;
    int v = (i < NN) ? g_deg[i] : 0;
    int s = v;
    #pragma unroll
    for (int o = 1; o < 32; o <<= 1) { int t = __shfl_up_sync(0xffffffffu, s, o); if (lane >= o) s += t; }
    __shared__ int wsum[32];
    if (lane == 31) wsum[wid] = s;
    __syncthreads();
    if (wid == 0) {
        int t = wsum[lane];
        #pragma unroll
        for (int o = 1; o < 32; o <<= 1) { int u = __shfl_up_sync(0xffffffffu, t, o); if (lane >= o) t += u; }
        wsum[lane] = t;
    }
    __syncthreads();
    int incl = s + (wid ? wsum[wid - 1] : 0);
    if (i < NN) g_off[i] = incl;
    if (threadIdx.x == 1023) g_bsum[blockIdx.x] = incl;
}

// ---- scan phase 2: to-exclusive + inline block bases + graph boundaries -----
__global__ void scan3_kernel(const void* __restrict__ ba) {
    __shared__ int sb[NBLK];
    for (int t = threadIdx.x; t < NBLK; t += blockDim.x) sb[t] = g_bsum[t];
    __syncthreads();
    int i = blockIdx.x * blockDim.x + threadIdx.x;
    if (i >= NN) return;
    int chunk = i >> 10;
    int base = 0;
    for (int j = 0; j < chunk; j++) base += sb[j];
    int e = g_off[i] - g_deg[i] + base;
    g_off[i] = e;
    g_cur[i] = e;
    int f = g_flagB;
    int b  = load_idx(ba, i, f);
    int bp = (i == 0) ? -1 : load_idx(ba, i - 1, f);
    for (int g = bp + 1; g <= b; g++) g_gstart[g] = i;
    if (i == NN - 1)
        for (int g = b + 1; g <= NG; g++) g_gstart[g] = NN;
}

// ---- adj build + t0 (norm-clamp of x into g_tha) fused by block range -------
__global__ void adj_t0_kernel(const void* __restrict__ ei, const float* __restrict__ x) {
    if (blockIdx.x < ADJ_BLKS) {
        int e = blockIdx.x * 256 + threadIdx.x;
        if (e >= NE) return;
        int f = g_flagE;
        int src = load_idx(ei, e, f);
        int dst = load_idx(ei, NE + e, f);
        int pos = atomicAdd(&g_cur[dst], 1);
        g_adj[pos] = src;
    } else {
        int gid = (blockIdx.x - ADJ_BLKS) * 256 + threadIdx.x;
        int node = gid >> 5, lane = gid & 31;
        if (node >= NN) return;
        float v = x[node * 32 + lane];
        float ss = v * v;
        #pragma unroll
        for (int o = 16; o; o >>= 1) ss += __shfl_xor_sync(0xffffffffu, ss, o);
        float nrm = sqrtf(ss);
        float s = (nrm > ACLAMP) ? (ACLAMP / nrm) : 1.0f;
        ((__half*)g_tha)[node * 32 + lane] = __float2half_rn(v * s);
    }
}

// ======== fused aggregation + GEMM + act + norm-clamp (+ pooling) ============
// Block = 64 nodes, 256 threads. Phase 1: warp-per-node edge gather (8 nodes
// per warp) from fp16 features. Phase 2: 64x64 GEMM with 4x4 micro-tiles.
// Epilogue: fp16 feature write (SRCB selects in/out buffers) or pooled atomics.
template <int DIMIN, int ACT, int POOL, int SRCB>
__global__ __launch_bounds__(256) void aggemm_kernel(const float* __restrict__ W,
                                                     const float* __restrict__ b,
                                                     const void* __restrict__ ba) {
    const __half2* __restrict__ tin = SRCB ? g_thb : g_tha;
    __half* __restrict__ tout = (__half*)(SRCB ? g_tha : g_thb);
    __shared__ float As[64 * 65];
    __shared__ __align__(16) float Ws[64 * 64];
    __shared__ float ssc[64];
    __shared__ int   sbid[64];
    int tid = threadIdx.x, wid = tid >> 5, lane = tid & 31;
    int row0 = blockIdx.x * 64;

    for (int idx = tid; idx < DIMIN * 64; idx += 256) Ws[idx] = W[idx];
    if (POOL && tid < 64) {
        int row = row0 + tid;
        sbid[tid] = (row < NN) ? load_idx(ba, row, g_flagB) : -1;
    }

    // ---- phase 1: gather ----
    if (DIMIN == 64) {
        #pragma unroll 1
        for (int p = 0; p < 8; p++) {
            int r = wid * 8 + p;
            int node = row0 + r;
            float ax = 0.0f, ay = 0.0f, bx = 0.0f, by = 0.0f;
            if (node < NN) {
                int o = g_off[node], d = g_deg[node];
                int j = 0;
                for (; j + 8 <= d; j += 8) {
                    int s0 = g_adj[o + j],     s1 = g_adj[o + j + 1];
                    int s2 = g_adj[o + j + 2], s3 = g_adj[o + j + 3];
                    int s4 = g_adj[o + j + 4], s5 = g_adj[o + j + 5];
                    int s6 = g_adj[o + j + 6], s7 = g_adj[o + j + 7];
                    float2 v0 = __half22float2(tin[s0 * 32 + lane]);
                    float2 v1 = __half22float2(tin[s1 * 32 + lane]);
                    float2 v2 = __half22float2(tin[s2 * 32 + lane]);
                    float2 v3 = __half22float2(tin[s3 * 32 + lane]);
                    float2 v4 = __half22float2(tin[s4 * 32 + lane]);
                    float2 v5 = __half22float2(tin[s5 * 32 + lane]);
                    float2 v6 = __half22float2(tin[s6 * 32 + lane]);
                    float2 v7 = __half22float2(tin[s7 * 32 + lane]);
                    ax += (v0.x + v1.x) + (v2.x + v3.x);
                    ay += (v0.y + v1.y) + (v2.y + v3.y);
                    bx += (v4.x + v5.x) + (v6.x + v7.x);
                    by += (v4.y + v5.y) + (v6.y + v7.y);
                }
                for (; j < d; j++) {
                    float2 v = __half22float2(tin[g_adj[o + j] * 32 + lane]);
                    ax += v.x; ay += v.y;
                }
                float inv = 1.0f / (float)((d > 0) ? d : 1);
                ax = (ax + bx) * inv;
                ay = (ay + by) * inv;
            }
            As[r * 65 + 2 * lane]     = ax;
            As[r * 65 + 2 * lane + 1] = ay;
        }
    } else {  // DIMIN == 32: half-warp (16 lanes x half2) per node
        int sub = lane >> 4, l16 = lane & 15;
        #pragma unroll 1
        for (int p = 0; p < 4; p++) {
            int r = wid * 8 + 2 * p + sub;
            int node = row0 + r;
            float ax = 0.0f, ay = 0.0f, bx = 0.0f, by = 0.0f;
            if (node < NN) {
                int o = g_off[node], d = g_deg[node];
                int j = 0;
                for (; j + 8 <= d; j += 8) {
                    int s0 = g_adj[o + j],     s1 = g_adj[o + j + 1];
                    int s2 = g_adj[o + j + 2], s3 = g_adj[o + j + 3];
                    int s4 = g_adj[o + j + 4], s5 = g_adj[o + j + 5];
                    int s6 = g_adj[o + j + 6], s7 = g_adj[o + j + 7];
                    float2 v0 = __half22float2(tin[s0 * 16 + l16]);
                    float2 v1 = __half22float2(tin[s1 * 16 + l16]);
                    float2 v2 = __half22float2(tin[s2 * 16 + l16]);
                    float2 v3 = __half22float2(tin[s3 * 16 + l16]);
                    float2 v4 = __half22float2(tin[s4 * 16 + l16]);
                    float2 v5 = __half22float2(tin[s5 * 16 + l16]);
                    float2 v6 = __half22float2(tin[s6 * 16 + l16]);
                    float2 v7 = __half22float2(tin[s7 * 16 + l16]);
                    ax += (v0.x + v1.x) + (v2.x + v3.x);
                    ay += (v0.y + v1.y) + (v2.y + v3.y);
                    bx += (v4.x + v5.x) + (v6.x + v7.x);
                    by += (v4.y + v5.y) + (v6.y + v7.y);
                }
                for (; j < d; j++) {
                    float2 v = __half22float2(tin[g_adj[o + j] * 16 + l16]);
                    ax += v.x; ay += v.y;
                }
                float inv = 1.0f / (float)((d > 0) ? d : 1);
                ax = (ax + bx) * inv;
                ay = (ay + by) * inv;
            }
            As[r * 65 + 2 * l16]     = ax;
            As[r * 65 + 2 * l16 + 1] = ay;
        }
    }
    __syncthreads();

    // ---- phase 2: GEMM ----
    int rb = (tid >> 4) * 4, cb = (tid & 15) * 4;
    float acc[4][4];
    #pragma unroll
    for (int i = 0; i < 4; i++)
        #pragma unroll
        for (int j = 0; j < 4; j++) acc[i][j] = b[cb + j];

    #pragma unroll 8
    for (int k = 0; k < DIMIN; k++) {
        float a0 = As[(rb + 0) * 65 + k];
        float a1 = As[(rb + 1) * 65 + k];
        float a2 = As[(rb + 2) * 65 + k];
        float a3 = As[(rb + 3) * 65 + k];
        float4 w = *(const float4*)&Ws[k * 64 + cb];
        acc[0][0] += a0 * w.x; acc[0][1] += a0 * w.y; acc[0][2] += a0 * w.z; acc[0][3] += a0 * w.w;
        acc[1][0] += a1 * w.x; acc[1][1] += a1 * w.y; acc[1][2] += a1 * w.z; acc[1][3] += a1 * w.w;
        acc[2][0] += a2 * w.x; acc[2][1] += a2 * w.y; acc[2][2] += a2 * w.z; acc[2][3] += a2 * w.w;
        acc[3][0] += a3 * w.x; acc[3][1] += a3 * w.y; acc[3][2] += a3 * w.z; acc[3][3] += a3 * w.w;
    }
    __syncthreads();

    #pragma unroll
    for (int i = 0; i < 4; i++)
        #pragma unroll
        for (int j = 0; j < 4; j++) {
            float u = acc[i][j];
            if (ACT) u = (u > 0.0f) ? u : 0.2f * u;
            As[(rb + i) * 65 + (cb + j)] = u;
        }
    __syncthreads();

    if (tid < 64) {
        float ss = 0.0f;
        #pragma unroll 8
        for (int c = 0; c < 64; c++) { float u = As[tid * 65 + c]; ss += u * u; }
        float nrm = sqrtf(ss);
        float s = (nrm > ACLAMP) ? (ACLAMP / nrm) : 1.0f;
        int row = row0 + tid;
        if (row < NN && g_deg[row] == 0) s = 0.0f;
        ssc[tid] = s;
    }
    __syncthreads();

    // ---- epilogue ----
    if (!POOL) {
        for (int idx = tid; idx < 64 * 64; idx += 256) {
            int r = idx >> 6, c = idx & 63;
            int row = row0 + r;
            if (row < NN) tout[row * 64 + c] = __float2half_rn(As[r * 65 + c] * ssc[r]);
        }
    } else {
        // run-length pool over sorted batch within the 64-row tile
        if (tid < 64) {
            int c = tid;
            int gprev = sbid[0];
            float acc2 = 0.0f;
            #pragma unroll 1
            for (int r = 0; r < 64; r++) {
                int g = sbid[r];
                if (g < 0) break;                   // rows past NN
                if (g != gprev) {
                    atomicAdd(&g_pool[gprev * 64 + c], acc2);
                    acc2 = 0.0f;
                    gprev = g;
                }
                acc2 += As[r * 65 + c] * ssc[r];
            }
            if (gprev >= 0) atomicAdd(&g_pool[gprev * 64 + c], acc2);
        }
    }
}

// ---------------- head: mean-pool -> clamp -> linear -> expmap0 -> proj ------
__global__ void final_kernel(const float* __restrict__ Wl,
                             const float* __restrict__ bl,
                             float* __restrict__ out) {
    __shared__ float sht[64];
    __shared__ float shz[10];
    __shared__ float shred[2];
    __shared__ float shF;
    int g = blockIdx.x, c = threadIdx.x;
    float cnt = (float)max(g_gstart[g + 1] - g_gstart[g], 1);
    float v = g_pool[g * 64 + c] / cnt;
    float ss = v * v;
    #pragma unroll
    for (int o = 16; o; o >>= 1) ss += __shfl_xor_sync(0xffffffffu, ss, o);
    if ((c & 31) == 0) shred[c >> 5] = ss;
    __syncthreads();
    float nrm = sqrtf(shred[0] + shred[1]);
    float s = (nrm > ACLAMP) ? (ACLAMP / nrm) : 1.0f;
    sht[c] = v * s;
    __syncthreads();
    if (c < 10) {
        float z = bl[c];
        #pragma unroll 8
        for (int k = 0; k < 64; k++) z += sht[k] * Wl[k * 10 + c];
        shz[c] = z;
    }
    __syncthreads();
    if (c == 0) {
        float s2 = 0.0f;
        #pragma unroll
        for (int j = 0; j < 10; j++) s2 += shz[j] * shz[j];
        float n2 = sqrtf(s2);
        float nn = fmaxf(n2, EPSF);
        float fac = tanhf(nn) / nn;
        float ny = fac * n2;
        float F = fac;
        if (ny > MAXNORM) F = fac * (MAXNORM / fmaxf(ny, EPSF));
        shF = F;
    }
    __syncthreads();
    if (c < 10) out[g * 10 + c] = shz[c] * shF;
}

// ---------------- launch ------------------------------------------------------
extern "C" void kernel_launch(void* const* d_in, const int* in_sizes, int n_in,
                              void* d_out, int out_size) {
    const float* x  = (const float*)d_in[0];
    const void*  ei = d_in[1];
    const void*  ba = d_in[2];
    const float* W1 = (const float*)d_in[3];
    const float* b1 = (const float*)d_in[4];
    const float* W2 = (const float*)d_in[5];
    const float* b2 = (const float*)d_in[6];
    const float* W3 = (const float*)d_in[7];
    const float* b3 = (const float*)d_in[8];
    const float* Wl = (const float*)d_in[9];
    const float* bl = (const float*)d_in[10];
    float* out = (float*)d_out;

    zero_kernel<<<(NN + 255) / 256, 256>>>((const int*)ei, (const int*)ba);
    deg_kernel<<<(NE + 255) / 256, 256>>>(ei);
    scan1_kernel<<<NBLK, 1024>>>();
    scan3_kernel<<<(NN + 255) / 256, 256>>>(ba);
    adj_t0_kernel<<<ADJ_BLKS + T0_BLKS, 256>>>(ei, x);

    const int GEMM_GRID = (NN + 63) / 64;
    aggemm_kernel<32, 1, 0, 0><<<GEMM_GRID, 256>>>(W1, b1, ba);  // tha -> thb
    aggemm_kernel<64, 1, 0, 1><<<GEMM_GRID, 256>>>(W2, b2, ba);  // thb -> tha
    aggemm_kernel<64, 0, 1, 0><<<GEMM_GRID, 256>>>(W3, b3, ba);  // tha -> pool

    final_kernel<<<NG, 64>>>(Wl, bl, out);
}

// round 8
// speedup vs baseline: 1.6507x; 1.6507x over previous
#include <cuda_runtime.h>
#include <cuda_fp16.h>
#include <math.h>

#define NN 50000
#define NE 1200000
#define NG 128
#define NBLK 49            // ceil(NN/1024)
#define ADJ_BLKS ((NE + 255) / 256)
#define T0_BLKS  ((NN + 7) / 8)        // warp-per-node, 8 nodes/block
#define EPSF 1e-7f
#define MAXNORM (1.0f - 1e-5f)
#define ACLAMP 6.1030338f  // arctanh(1 - 1e-5)

// ---------------- scratch (static device globals; no allocation) -------------
__device__ int     g_flagE;
__device__ int     g_flagB;
__device__ int     g_deg[NN];
__device__ int     g_off[NN];
__device__ int     g_cur[NN];
__device__ int     g_adj[NE];
__device__ int     g_bsum[64];
__device__ int     g_gstart[NG + 1];
__device__ float   g_pool[NG * 64];
__device__ __half2 g_th2[NN * 32];   // node features fp16 (stride 16 or 32 half2)
__device__ float   g_agg[NN * 64];

#define G_TH ((__half*)g_th2)

__device__ __forceinline__ int load_idx(const void* p, int i, int flag64) {
    return flag64 ? (int)((const long long*)p)[i] : ((const int*)p)[i];
}

// ---------------- zero + dtype detection (block 0) ---------------------------
// int64-vs-int32 sniffer: odd 32-bit words of small int64 values are all zero.
// Windows are mid-array so the sorted batch head (all zeros) can't fool it.
__global__ void zero_kernel(const int* __restrict__ ei, const int* __restrict__ ba) {
    int i = blockIdx.x * blockDim.x + threadIdx.x;
    if (i < NN)      g_deg[i]  = 0;
    if (i < NG * 64) g_pool[i] = 0.0f;
    if (blockIdx.x == 0) {
        __shared__ int nzE, nzB;
        if (threadIdx.x == 0) { nzE = 0; nzB = 0; }
        __syncthreads();
        for (int w = NE + 1 + 2 * threadIdx.x; w < NE + 2048; w += 2 * blockDim.x)
            if (ei[w] != 0) atomicOr(&nzE, 1);
        for (int w = 48001 + 2 * threadIdx.x; w < 50000; w += 2 * blockDim.x)
            if (ba[w] != 0) atomicOr(&nzB, 1);
        __syncthreads();
        if (threadIdx.x == 0) { g_flagE = (nzE == 0); g_flagB = (nzB == 0); }
    }
}

__global__ void deg_kernel(const void* __restrict__ ei) {
    int e = blockIdx.x * blockDim.x + threadIdx.x;
    if (e >= NE) return;
    int dst = load_idx(ei, NE + e, g_flagE);
    atomicAdd(&g_deg[dst], 1);
}

// ---- scan phase 1: 49 blocks x 1024, per-block inclusive scan ---------------
__global__ void scan1_kernel() {
    int i = blockIdx.x * 1024 + threadIdx.x;
    int lane = threadIdx.x & 31, wid = threadIdx.x >> 5;
    int v = (i < NN) ? g_deg[i] : 0;
    int s = v;
    #pragma unroll
    for (int o = 1; o < 32; o <<= 1) { int t = __shfl_up_sync(0xffffffffu, s, o); if (lane >= o) s += t; }
    __shared__ int wsum[32];
    if (lane == 31) wsum[wid] = s;
    __syncthreads();
    if (wid == 0) {
        int t = wsum[lane];
        #pragma unroll
        for (int o = 1; o < 32; o <<= 1) { int u = __shfl_up_sync(0xffffffffu, t, o); if (lane >= o) t += u; }
        wsum[lane] = t;
    }
    __syncthreads();
    int incl = s + (wid ? wsum[wid - 1] : 0);
    if (i < NN) g_off[i] = incl;
    if (threadIdx.x == 1023) g_bsum[blockIdx.x] = incl;
}

// ---- scan phase 2: to-exclusive + inline block bases + graph boundaries -----
__global__ void scan3_kernel(const void* __restrict__ ba) {
    __shared__ int sb[NBLK];
    for (int t = threadIdx.x; t < NBLK; t += blockDim.x) sb[t] = g_bsum[t];
    __syncthreads();
    int i = blockIdx.x * blockDim.x + threadIdx.x;
    if (i >= NN) return;
    int chunk = i >> 10;
    int base = 0;
    for (int j = 0; j < chunk; j++) base += sb[j];
    int e = g_off[i] - g_deg[i] + base;
    g_off[i] = e;
    g_cur[i] = e;
    int f = g_flagB;
    int b  = load_idx(ba, i, f);
    int bp = (i == 0) ? -1 : load_idx(ba, i - 1, f);
    for (int g = bp + 1; g <= b; g++) g_gstart[g] = i;
    if (i == NN - 1)
        for (int g = b + 1; g <= NG; g++) g_gstart[g] = NN;
}

// ---- adj build + t0 (norm-clamp of x into fp16 features) fused --------------
__global__ void adj_t0_kernel(const void* __restrict__ ei, const float* __restrict__ x) {
    if (blockIdx.x < ADJ_BLKS) {
        int e = blockIdx.x * 256 + threadIdx.x;
        if (e >= NE) return;
        int f = g_flagE;
        int src = load_idx(ei, e, f);
        int dst = load_idx(ei, NE + e, f);
        int pos = atomicAdd(&g_cur[dst], 1);
        g_adj[pos] = src;
    } else {
        int gid = (blockIdx.x - ADJ_BLKS) * 256 + threadIdx.x;
        int node = gid >> 5, lane = gid & 31;
        if (node >= NN) return;
        float v = x[node * 32 + lane];
        float ss = v * v;
        #pragma unroll
        for (int o = 16; o; o >>= 1) ss += __shfl_xor_sync(0xffffffffu, ss, o);
        float nrm = sqrtf(ss);
        float s = (nrm > ACLAMP) ? (ACLAMP / nrm) : 1.0f;
        G_TH[node * 32 + lane] = __float2half_rn(v * s);
    }
}

// ------- mean aggregation: 32-d path, HALF-WARP (16 lanes x half2) per node --
__global__ void agg32_kernel() {
    int gid = blockIdx.x * blockDim.x + threadIdx.x;
    int node = gid >> 4, lane = gid & 15;
    if (node >= NN) return;
    const __half2* __restrict__ tin = g_th2;   // 16 half2 per node
    int o = g_off[node];
    int d = g_deg[node];
    float ax = 0.0f, ay = 0.0f, bx = 0.0f, by = 0.0f;
    int j = 0;
    for (; j + 8 <= d; j += 8) {
        int s0 = g_adj[o + j],     s1 = g_adj[o + j + 1];
        int s2 = g_adj[o + j + 2], s3 = g_adj[o + j + 3];
        int s4 = g_adj[o + j + 4], s5 = g_adj[o + j + 5];
        int s6 = g_adj[o + j + 6], s7 = g_adj[o + j + 7];
        float2 v0 = __half22float2(tin[s0 * 16 + lane]);
        float2 v1 = __half22float2(tin[s1 * 16 + lane]);
        float2 v2 = __half22float2(tin[s2 * 16 + lane]);
        float2 v3 = __half22float2(tin[s3 * 16 + lane]);
        float2 v4 = __half22float2(tin[s4 * 16 + lane]);
        float2 v5 = __half22float2(tin[s5 * 16 + lane]);
        float2 v6 = __half22float2(tin[s6 * 16 + lane]);
        float2 v7 = __half22float2(tin[s7 * 16 + lane]);
        ax += (v0.x + v1.x) + (v2.x + v3.x);
        ay += (v0.y + v1.y) + (v2.y + v3.y);
        bx += (v4.x + v5.x) + (v6.x + v7.x);
        by += (v4.y + v5.y) + (v6.y + v7.y);
    }
    for (; j < d; j++) {
        float2 v = __half22float2(tin[g_adj[o + j] * 16 + lane]);
        ax += v.x; ay += v.y;
    }
    float inv = 1.0f / (float)((d > 0) ? d : 1);
    float2 r;
    r.x = (ax + bx) * inv;
    r.y = (ay + by) * inv;
    ((float2*)g_agg)[node * 16 + lane] = r;
}

// ------- mean aggregation: 64-d path, warp (32 lanes x half2) per node -------
__global__ void agg64_kernel() {
    int gid = blockIdx.x * blockDim.x + threadIdx.x;
    int node = gid >> 5, lane = gid & 31;
    if (node >= NN) return;
    const __half2* __restrict__ tin = g_th2;   // 32 half2 per node
    int o = g_off[node];
    int d = g_deg[node];
    float ax = 0.0f, ay = 0.0f, bx = 0.0f, by = 0.0f;
    int j = 0;
    for (; j + 8 <= d; j += 8) {
        int s0 = g_adj[o + j],     s1 = g_adj[o + j + 1];
        int s2 = g_adj[o + j + 2], s3 = g_adj[o + j + 3];
        int s4 = g_adj[o + j + 4], s5 = g_adj[o + j + 5];
        int s6 = g_adj[o + j + 6], s7 = g_adj[o + j + 7];
        float2 v0 = __half22float2(tin[s0 * 32 + lane]);
        float2 v1 = __half22float2(tin[s1 * 32 + lane]);
        float2 v2 = __half22float2(tin[s2 * 32 + lane]);
        float2 v3 = __half22float2(tin[s3 * 32 + lane]);
        float2 v4 = __half22float2(tin[s4 * 32 + lane]);
        float2 v5 = __half22float2(tin[s5 * 32 + lane]);
        float2 v6 = __half22float2(tin[s6 * 32 + lane]);
        float2 v7 = __half22float2(tin[s7 * 32 + lane]);
        ax += (v0.x + v1.x) + (v2.x + v3.x);
        ay += (v0.y + v1.y) + (v2.y + v3.y);
        bx += (v4.x + v5.x) + (v6.x + v7.x);
        by += (v4.y + v5.y) + (v6.y + v7.y);
    }
    for (; j < d; j++) {
        float2 v = __half22float2(tin[g_adj[o + j] * 32 + lane]);
        ax += v.x; ay += v.y;
    }
    float inv = 1.0f / (float)((d > 0) ? d : 1);
    float2 r;
    r.x = (ax + bx) * inv;
    r.y = (ay + by) * inv;
    ((float2*)g_agg)[node * 32 + lane] = r;
}

// ---------- GEMM (agg @ W + b) + act + norm-clamp + deg==0 zeroing -----------
template <int DIMIN, int ACT>
__global__ __launch_bounds__(256) void gemm_kernel(const float* __restrict__ W,
                                                   const float* __restrict__ b) {
    __shared__ float As[64 * 65];
    __shared__ __align__(16) float Ws[64 * 64];
    __shared__ float ssc[64];
    int tid = threadIdx.x;
    int row0 = blockIdx.x * 64;

    // vectorized tile load (g_agg rows are 16B-aligned for both DIMIN)
    const int NV = 64 * DIMIN / 4;
    for (int idx = tid; idx < NV; idx += 256) {
        int r = idx / (DIMIN / 4), c4 = idx % (DIMIN / 4);
        int row = row0 + r;
        float4 v = (row < NN) ? ((const float4*)g_agg)[row * (DIMIN / 4) + c4]
                              : make_float4(0.f, 0.f, 0.f, 0.f);
        float* dstp = &As[r * 65 + c4 * 4];
        dstp[0] = v.x; dstp[1] = v.y; dstp[2] = v.z; dstp[3] = v.w;
    }
    for (int idx = tid; idx < DIMIN * 16; idx += 256)
        ((float4*)Ws)[idx] = ((const float4*)W)[idx];
    __syncthreads();

    int rb = (tid >> 4) * 4, cb = (tid & 15) * 4;
    float acc[4][4];
    #pragma unroll
    for (int i = 0; i < 4; i++)
        #pragma unroll
        for (int j = 0; j < 4; j++) acc[i][j] = b[cb + j];

    #pragma unroll 8
    for (int k = 0; k < DIMIN; k++) {
        float a0 = As[(rb + 0) * 65 + k];
        float a1 = As[(rb + 1) * 65 + k];
        float a2 = As[(rb + 2) * 65 + k];
        float a3 = As[(rb + 3) * 65 + k];
        float4 w = *(const float4*)&Ws[k * 64 + cb];
        acc[0][0] += a0 * w.x; acc[0][1] += a0 * w.y; acc[0][2] += a0 * w.z; acc[0][3] += a0 * w.w;
        acc[1][0] += a1 * w.x; acc[1][1] += a1 * w.y; acc[1][2] += a1 * w.z; acc[1][3] += a1 * w.w;
        acc[2][0] += a2 * w.x; acc[2][1] += a2 * w.y; acc[2][2] += a2 * w.z; acc[2][3] += a2 * w.w;
        acc[3][0] += a3 * w.x; acc[3][1] += a3 * w.y; acc[3][2] += a3 * w.z; acc[3][3] += a3 * w.w;
    }
    __syncthreads();

    #pragma unroll
    for (int i = 0; i < 4; i++)
        #pragma unroll
        for (int j = 0; j < 4; j++) {
            float u = acc[i][j];
            if (ACT) u = (u > 0.0f) ? u : 0.2f * u;
            As[(rb + i) * 65 + (cb + j)] = u;
        }
    __syncthreads();

    if (tid < 64) {
        float ss = 0.0f;
        #pragma unroll 8
        for (int c = 0; c < 64; c++) { float u = As[tid * 65 + c]; ss += u * u; }
        float nrm = sqrtf(ss);
        float s = (nrm > ACLAMP) ? (ACLAMP / nrm) : 1.0f;
        int row = row0 + tid;
        if (row < NN && g_deg[row] == 0) s = 0.0f;
        ssc[tid] = s;
    }
    __syncthreads();

    for (int idx = tid; idx < 64 * 64; idx += 256) {
        int r = idx >> 6, c = idx & 63;
        int row = row0 + r;
        if (row < NN) G_TH[row * 64 + c] = __float2half_rn(As[r * 65 + c] * ssc[r]);
    }
}

// ------- graph pooling: 4 independent 32-node run-length subranges / block ---
__global__ void pool_kernel(const void* __restrict__ ba) {
    int c = threadIdx.x & 63;              // column 0..63
    int q = threadIdx.x >> 6;              // subrange 0..3
    int n0 = blockIdx.x * 128 + q * 32;
    int n1 = min(n0 + 32, NN);
    if (n0 >= NN) return;
    int f = g_flagB;
    int gprev = load_idx(ba, n0, f);
    float acc = 0.0f;
    for (int n = n0; n < n1; n++) {
        int g = load_idx(ba, n, f);
        if (g != gprev) {
            atomicAdd(&g_pool[gprev * 64 + c], acc);
            acc = 0.0f;
            gprev = g;
        }
        acc += __half2float(G_TH[n * 64 + c]);
    }
    atomicAdd(&g_pool[gprev * 64 + c], acc);
}

// ---------------- head: mean-pool -> clamp -> linear -> expmap0 -> proj ------
__global__ void final_kernel(const float* __restrict__ Wl,
                             const float* __restrict__ bl,
                             float* __restrict__ out) {
    __shared__ float sht[64];
    __shared__ float shz[10];
    __shared__ float shred[2];
    __shared__ float shF;
    int g = blockIdx.x, c = threadIdx.x;
    float cnt = (float)max(g_gstart[g + 1] - g_gstart[g], 1);
    float v = g_pool[g * 64 + c] / cnt;
    float ss = v * v;
    #pragma unroll
    for (int o = 16; o; o >>= 1) ss += __shfl_xor_sync(0xffffffffu, ss, o);
    if ((c & 31) == 0) shred[c >> 5] = ss;
    __syncthreads();
    float nrm = sqrtf(shred[0] + shred[1]);
    float s = (nrm > ACLAMP) ? (ACLAMP / nrm) : 1.0f;
    sht[c] = v * s;
    __syncthreads();
    if (c < 10) {
        float z = bl[c];
        #pragma unroll 8
        for (int k = 0; k < 64; k++) z += sht[k] * Wl[k * 10 + c];
        shz[c] = z;
    }
    __syncthreads();
    if (c == 0) {
        float s2 = 0.0f;
        #pragma unroll
        for (int j = 0; j < 10; j++) s2 += shz[j] * shz[j];
        float n2 = sqrtf(s2);
        float nn = fmaxf(n2, EPSF);
        float fac = tanhf(nn) / nn;
        float ny = fac * n2;
        float F = fac;
        if (ny > MAXNORM) F = fac * (MAXNORM / fmaxf(ny, EPSF));
        shF = F;
    }
    __syncthreads();
    if (c < 10) out[g * 10 + c] = shz[c] * shF;
}

// ---------------- launch ------------------------------------------------------
extern "C" void kernel_launch(void* const* d_in, const int* in_sizes, int n_in,
                              void* d_out, int out_size) {
    const float* x  = (const float*)d_in[0];
    const void*  ei = d_in[1];
    const void*  ba = d_in[2];
    const float* W1 = (const float*)d_in[3];
    const float* b1 = (const float*)d_in[4];
    const float* W2 = (const float*)d_in[5];
    const float* b2 = (const float*)d_in[6];
    const float* W3 = (const float*)d_in[7];
    const float* b3 = (const float*)d_in[8];
    const float* Wl = (const float*)d_in[9];
    const float* bl = (const float*)d_in[10];
    float* out = (float*)d_out;

    zero_kernel<<<(NN + 255) / 256, 256>>>((const int*)ei, (const int*)ba);
    deg_kernel<<<(NE + 255) / 256, 256>>>(ei);
    scan1_kernel<<<NBLK, 1024>>>();
    scan3_kernel<<<(NN + 255) / 256, 256>>>(ba);
    adj_t0_kernel<<<ADJ_BLKS + T0_BLKS, 256>>>(ei, x);

    const int GEMM_GRID = (NN + 63) / 64;

    agg32_kernel<<<(NN * 16 + 255) / 256, 256>>>();
    gemm_kernel<32, 1><<<GEMM_GRID, 256>>>(W1, b1);
    agg64_kernel<<<(NN * 32 + 255) / 256, 256>>>();
    gemm_kernel<64, 1><<<GEMM_GRID, 256>>>(W2, b2);
    agg64_kernel<<<(NN * 32 + 255) / 256, 256>>>();
    gemm_kernel<64, 0><<<GEMM_GRID, 256>>>(W3, b3);

    pool_kernel<<<(NN + 127) / 128, 256>>>(ba);
    final_kernel<<<NG, 64>>>(Wl, bl, out);
}

// round 9
// speedup vs baseline: 1.7432x; 1.0560x over previous
#include <cuda_runtime.h>
#include <cuda_fp16.h>
#include <math.h>

#define NN 50000
#define NE 1200000
#define NG 128
#define NBLK 49            // ceil(NN/1024)
#define NE4 (NE / 4)       // 300000 edge quads
#define EQ_BLKS ((NE4 + 255) / 256)
#define T0_BLKS ((NN + 7) / 8)         // warp-per-node, 8 nodes/block
#define EPSF 1e-7f
#define MAXNORM (1.0f - 1e-5f)
#define ACLAMP 6.1030338f  // arctanh(1 - 1e-5)

// ---------------- scratch (static device globals; no allocation) -------------
__device__ int     g_flagE;
__device__ int     g_flagB;
__device__ int     g_deg[NN];
__device__ int     g_off[NN];
__device__ int     g_cur[NN];
__device__ int     g_adj[NE];
__device__ int     g_binc[NBLK];               // inclusive block sums
__device__ volatile int g_bflag[NBLK];         // lookback flags
__device__ int     g_gstart[NG + 1];
__device__ float   g_pool[NG * 64];
__device__ __half2 g_th2[NN * 32];   // node features fp16 (stride 16 or 32 half2)
__device__ float   g_agg[NN * 64];

#define G_TH ((__half*)g_th2)

__device__ __forceinline__ int load_idx(const void* p, int i, int flag64) {
    return flag64 ? (int)((const long long*)p)[i] : ((const int*)p)[i];
}

// ---------------- zero + dtype detection (block 0) ---------------------------
// int64-vs-int32 sniffer: odd 32-bit words of small int64 values are all zero.
// Windows are mid-array so the sorted batch head (all zeros) can't fool it.
__global__ void zero_kernel(const int* __restrict__ ei, const int* __restrict__ ba) {
    int i = blockIdx.x * blockDim.x + threadIdx.x;
    if (i < NN)      g_deg[i]  = 0;
    if (i < NG * 64) g_pool[i] = 0.0f;
    if (i < NBLK)    g_bflag[i] = 0;
    if (blockIdx.x == 0) {
        __shared__ int nzE, nzB;
        if (threadIdx.x == 0) { nzE = 0; nzB = 0; }
        __syncthreads();
        for (int w = NE + 1 + 2 * threadIdx.x; w < NE + 2048; w += 2 * blockDim.x)
            if (ei[w] != 0) atomicOr(&nzE, 1);
        for (int w = 48001 + 2 * threadIdx.x; w < 50000; w += 2 * blockDim.x)
            if (ba[w] != 0) atomicOr(&nzB, 1);
        __syncthreads();
        if (threadIdx.x == 0) { g_flagE = (nzE == 0); g_flagB = (nzB == 0); }
    }
}

// ---- degree count: 4 edges per thread, vectorized loads ---------------------
__global__ void deg_kernel(const void* __restrict__ ei) {
    int t = blockIdx.x * blockDim.x + threadIdx.x;
    if (t >= NE4) return;
    if (!g_flagE) {
        int4 d = ((const int4*)((const int*)ei + NE))[t];
        atomicAdd(&g_deg[d.x], 1);
        atomicAdd(&g_deg[d.y], 1);
        atomicAdd(&g_deg[d.z], 1);
        atomicAdd(&g_deg[d.w], 1);
    } else {
        const int4* p = (const int4*)((const long long*)ei + NE);
        int4 a = p[2 * t], b = p[2 * t + 1];
        atomicAdd(&g_deg[a.x], 1);
        atomicAdd(&g_deg[a.z], 1);
        atomicAdd(&g_deg[b.x], 1);
        atomicAdd(&g_deg[b.z], 1);
    }
}

// ---- single-launch exclusive scan (decoupled lookback) + graph boundaries ---
__global__ void scan_kernel(const void* __restrict__ ba) {
    int bid = blockIdx.x;
    int i = bid * 1024 + threadIdx.x;
    int lane = threadIdx.x & 31, wid = threadIdx.x >> 5;
    int v = (i < NN) ? g_deg[i] : 0;
    int s = v;
    #pragma unroll
    for (int o = 1; o < 32; o <<= 1) { int t = __shfl_up_sync(0xffffffffu, s, o); if (lane >= o) s += t; }
    __shared__ int wsum[32];
    __shared__ int sbase;
    if (lane == 31) wsum[wid] = s;
    if (threadIdx.x == 0) sbase = 0;
    __syncthreads();
    if (wid == 0) {
        int t = wsum[lane];
        #pragma unroll
        for (int o = 1; o < 32; o <<= 1) { int u = __shfl_up_sync(0xffffffffu, t, o); if (lane >= o) t += u; }
        wsum[lane] = t;
    }
    __syncthreads();
    int incl = s + (wid ? wsum[wid - 1] : 0);

    // publish block total, then gather predecessor bases (all blocks co-resident)
    if (threadIdx.x == 1023) {
        g_binc[bid] = incl;
        __threadfence();
        g_bflag[bid] = 1;
    }
    if (threadIdx.x < bid) {                    // bid <= 48
        while (g_bflag[threadIdx.x] == 0) { }
        __threadfence();
        atomicAdd(&sbase, g_binc[threadIdx.x]);
    }
    __syncthreads();

    if (i < NN) {
        int e = incl - v + sbase;
        g_off[i] = e;
        g_cur[i] = e;
        int f = g_flagB;
        int b  = load_idx(ba, i, f);
        int bp = (i == 0) ? -1 : load_idx(ba, i - 1, f);
        for (int g = bp + 1; g <= b; g++) g_gstart[g] = i;
        if (i == NN - 1)
            for (int g = b + 1; g <= NG; g++) g_gstart[g] = NN;
    }
}

// ---- adj build (4 edges/thread) + t0 (norm-clamp into fp16) fused -----------
__global__ void adj_t0_kernel(const void* __restrict__ ei, const float* __restrict__ x) {
    if (blockIdx.x < EQ_BLKS) {
        int t = blockIdx.x * 256 + threadIdx.x;
        if (t >= NE4) return;
        int s0, s1, s2, s3, d0, d1, d2, d3;
        if (!g_flagE) {
            int4 sv = ((const int4*)ei)[t];
            int4 dv = ((const int4*)((const int*)ei + NE))[t];
            s0 = sv.x; s1 = sv.y; s2 = sv.z; s3 = sv.w;
            d0 = dv.x; d1 = dv.y; d2 = dv.z; d3 = dv.w;
        } else {
            const int4* ps = (const int4*)ei;
            const int4* pd = (const int4*)((const long long*)ei + NE);
            int4 sa = ps[2 * t], sb = ps[2 * t + 1];
            int4 da = pd[2 * t], db = pd[2 * t + 1];
            s0 = sa.x; s1 = sa.z; s2 = sb.x; s3 = sb.z;
            d0 = da.x; d1 = da.z; d2 = db.x; d3 = db.z;
        }
        g_adj[atomicAdd(&g_cur[d0], 1)] = s0;
        g_adj[atomicAdd(&g_cur[d1], 1)] = s1;
        g_adj[atomicAdd(&g_cur[d2], 1)] = s2;
        g_adj[atomicAdd(&g_cur[d3], 1)] = s3;
    } else {
        int gid = (blockIdx.x - EQ_BLKS) * 256 + threadIdx.x;
        int node = gid >> 5, lane = gid & 31;
        if (node >= NN) return;
        float v = x[node * 32 + lane];
        float ss = v * v;
        #pragma unroll
        for (int o = 16; o; o >>= 1) ss += __shfl_xor_sync(0xffffffffu, ss, o);
        float nrm = sqrtf(ss);
        float s = (nrm > ACLAMP) ? (ACLAMP / nrm) : 1.0f;
        G_TH[node * 32 + lane] = __float2half_rn(v * s);
    }
}

// ------- mean aggregation: 32-d path, HALF-WARP (16 lanes x half2) per node --
__global__ void agg32_kernel() {
    int gid = blockIdx.x * blockDim.x + threadIdx.x;
    int node = gid >> 4, lane = gid & 15;
    if (node >= NN) return;
    const __half2* __restrict__ tin = g_th2;   // 16 half2 per node
    int o = g_off[node];
    int d = g_deg[node];
    float ax = 0.0f, ay = 0.0f, bx = 0.0f, by = 0.0f;
    int j = 0;
    for (; j + 8 <= d; j += 8) {
        int s0 = g_adj[o + j],     s1 = g_adj[o + j + 1];
        int s2 = g_adj[o + j + 2], s3 = g_adj[o + j + 3];
        int s4 = g_adj[o + j + 4], s5 = g_adj[o + j + 5];
        int s6 = g_adj[o + j + 6], s7 = g_adj[o + j + 7];
        float2 v0 = __half22float2(tin[s0 * 16 + lane]);
        float2 v1 = __half22float2(tin[s1 * 16 + lane]);
        float2 v2 = __half22float2(tin[s2 * 16 + lane]);
        float2 v3 = __half22float2(tin[s3 * 16 + lane]);
        float2 v4 = __half22float2(tin[s4 * 16 + lane]);
        float2 v5 = __half22float2(tin[s5 * 16 + lane]);
        float2 v6 = __half22float2(tin[s6 * 16 + lane]);
        float2 v7 = __half22float2(tin[s7 * 16 + lane]);
        ax += (v0.x + v1.x) + (v2.x + v3.x);
        ay += (v0.y + v1.y) + (v2.y + v3.y);
        bx += (v4.x + v5.x) + (v6.x + v7.x);
        by += (v4.y + v5.y) + (v6.y + v7.y);
    }
    for (; j < d; j++) {
        float2 v = __half22float2(tin[g_adj[o + j] * 16 + lane]);
        ax += v.x; ay += v.y;
    }
    float inv = 1.0f / (float)((d > 0) ? d : 1);
    float2 r;
    r.x = (ax + bx) * inv;
    r.y = (ay + by) * inv;
    ((float2*)g_agg)[node * 16 + lane] = r;
}

// ------- mean aggregation: 64-d path, warp (32 lanes x half2) per node -------
__global__ void agg64_kernel() {
    int gid = blockIdx.x * blockDim.x + threadIdx.x;
    int node = gid >> 5, lane = gid & 31;
    if (node >= NN) return;
    const __half2* __restrict__ tin = g_th2;   // 32 half2 per node
    int o = g_off[node];
    int d = g_deg[node];
    float ax = 0.0f, ay = 0.0f, bx = 0.0f, by = 0.0f;
    int j = 0;
    for (; j + 8 <= d; j += 8) {
        int s0 = g_adj[o + j],     s1 = g_adj[o + j + 1];
        int s2 = g_adj[o + j + 2], s3 = g_adj[o + j + 3];
        int s4 = g_adj[o + j + 4], s5 = g_adj[o + j + 5];
        int s6 = g_adj[o + j + 6], s7 = g_adj[o + j + 7];
        float2 v0 = __half22float2(tin[s0 * 32 + lane]);
        float2 v1 = __half22float2(tin[s1 * 32 + lane]);
        float2 v2 = __half22float2(tin[s2 * 32 + lane]);
        float2 v3 = __half22float2(tin[s3 * 32 + lane]);
        float2 v4 = __half22float2(tin[s4 * 32 + lane]);
        float2 v5 = __half22float2(tin[s5 * 32 + lane]);
        float2 v6 = __half22float2(tin[s6 * 32 + lane]);
        float2 v7 = __half22float2(tin[s7 * 32 + lane]);
        ax += (v0.x + v1.x) + (v2.x + v3.x);
        ay += (v0.y + v1.y) + (v2.y + v3.y);
        bx += (v4.x + v5.x) + (v6.x + v7.x);
        by += (v4.y + v5.y) + (v6.y + v7.y);
    }
    for (; j < d; j++) {
        float2 v = __half22float2(tin[g_adj[o + j] * 32 + lane]);
        ax += v.x; ay += v.y;
    }
    float inv = 1.0f / (float)((d > 0) ? d : 1);
    float2 r;
    r.x = (ax + bx) * inv;
    r.y = (ay + by) * inv;
    ((float2*)g_agg)[node * 32 + lane] = r;
}

// ---------- GEMM (agg @ W + b) + act + norm-clamp + deg==0 zeroing -----------
// POOL=1: epilogue run-length pools into g_pool instead of writing features.
template <int DIMIN, int ACT, int POOL>
__global__ __launch_bounds__(256) void gemm_kernel(const float* __restrict__ W,
                                                   const float* __restrict__ b,
                                                   const void* __restrict__ ba) {
    __shared__ float As[64 * 65];
    __shared__ __align__(16) float Ws[64 * 64];
    __shared__ float ssc[64];
    __shared__ int   sbid[64];
    int tid = threadIdx.x;
    int row0 = blockIdx.x * 64;

    const int NV = 64 * DIMIN / 4;
    for (int idx = tid; idx < NV; idx += 256) {
        int r = idx / (DIMIN / 4), c4 = idx % (DIMIN / 4);
        int row = row0 + r;
        float4 v = (row < NN) ? ((const float4*)g_agg)[row * (DIMIN / 4) + c4]
                              : make_float4(0.f, 0.f, 0.f, 0.f);
        float* dstp = &As[r * 65 + c4 * 4];
        dstp[0] = v.x; dstp[1] = v.y; dstp[2] = v.z; dstp[3] = v.w;
    }
    for (int idx = tid; idx < DIMIN * 16; idx += 256)
        ((float4*)Ws)[idx] = ((const float4*)W)[idx];
    if (POOL && tid < 64) {
        int row = row0 + tid;
        sbid[tid] = (row < NN) ? load_idx(ba, row, g_flagB) : -1;
    }
    __syncthreads();

    int rb = (tid >> 4) * 4, cb = (tid & 15) * 4;
    float acc[4][4];
    #pragma unroll
    for (int i = 0; i < 4; i++)
        #pragma unroll
        for (int j = 0; j < 4; j++) acc[i][j] = b[cb + j];

    #pragma unroll 8
    for (int k = 0; k < DIMIN; k++) {
        float a0 = As[(rb + 0) * 65 + k];
        float a1 = As[(rb + 1) * 65 + k];
        float a2 = As[(rb + 2) * 65 + k];
        float a3 = As[(rb + 3) * 65 + k];
        float4 w = *(const float4*)&Ws[k * 64 + cb];
        acc[0][0] += a0 * w.x; acc[0][1] += a0 * w.y; acc[0][2] += a0 * w.z; acc[0][3] += a0 * w.w;
        acc[1][0] += a1 * w.x; acc[1][1] += a1 * w.y; acc[1][2] += a1 * w.z; acc[1][3] += a1 * w.w;
        acc[2][0] += a2 * w.x; acc[2][1] += a2 * w.y; acc[2][2] += a2 * w.z; acc[2][3] += a2 * w.w;
        acc[3][0] += a3 * w.x; acc[3][1] += a3 * w.y; acc[3][2] += a3 * w.z; acc[3][3] += a3 * w.w;
    }
    __syncthreads();

    #pragma unroll
    for (int i = 0; i < 4; i++)
        #pragma unroll
        for (int j = 0; j < 4; j++) {
            float u = acc[i][j];
            if (ACT) u = (u > 0.0f) ? u : 0.2f * u;
            As[(rb + i) * 65 + (cb + j)] = u;
        }
    __syncthreads();

    if (tid < 64) {
        float ss = 0.0f;
        #pragma unroll 8
        for (int c = 0; c < 64; c++) { float u = As[tid * 65 + c]; ss += u * u; }
        float nrm = sqrtf(ss);
        float s = (nrm > ACLAMP) ? (ACLAMP / nrm) : 1.0f;
        int row = row0 + tid;
        if (row < NN && g_deg[row] == 0) s = 0.0f;
        ssc[tid] = s;
    }
    __syncthreads();

    if (!POOL) {
        for (int idx = tid; idx < 64 * 64; idx += 256) {
            int r = idx >> 6, c = idx & 63;
            int row = row0 + r;
            if (row < NN) G_TH[row * 64 + c] = __float2half_rn(As[r * 65 + c] * ssc[r]);
        }
    } else {
        // run-length pool over sorted batch within the 64-row tile
        if (tid < 64) {
            int c = tid;
            int gprev = sbid[0];
            float acc2 = 0.0f;
            #pragma unroll 1
            for (int r = 0; r < 64; r++) {
                int g = sbid[r];
                if (g < 0) break;
                if (g != gprev) {
                    atomicAdd(&g_pool[gprev * 64 + c], acc2);
                    acc2 = 0.0f;
                    gprev = g;
                }
                acc2 += As[r * 65 + c] * ssc[r];
            }
            if (gprev >= 0) atomicAdd(&g_pool[gprev * 64 + c], acc2);
        }
    }
}

// ---------------- head: mean-pool -> clamp -> linear -> expmap0 -> proj ------
__global__ void final_kernel(const float* __restrict__ Wl,
                             const float* __restrict__ bl,
                             float* __restrict__ out) {
    __shared__ float sht[64];
    __shared__ float shz[10];
    __shared__ float shred[2];
    __shared__ float shF;
    int g = blockIdx.x, c = threadIdx.x;
    float cnt = (float)max(g_gstart[g + 1] - g_gstart[g], 1);
    float v = g_pool[g * 64 + c] / cnt;
    float ss = v * v;
    #pragma unroll
    for (int o = 16; o; o >>= 1) ss += __shfl_xor_sync(0xffffffffu, ss, o);
    if ((c & 31) == 0) shred[c >> 5] = ss;
    __syncthreads();
    float nrm = sqrtf(shred[0] + shred[1]);
    float s = (nrm > ACLAMP) ? (ACLAMP / nrm) : 1.0f;
    sht[c] = v * s;
    __syncthreads();
    if (c < 10) {
        float z = bl[c];
        #pragma unroll 8
        for (int k = 0; k < 64; k++) z += sht[k] * Wl[k * 10 + c];
        shz[c] = z;
    }
    __syncthreads();
    if (c == 0) {
        float s2 = 0.0f;
        #pragma unroll
        for (int j = 0; j < 10; j++) s2 += shz[j] * shz[j];
        float n2 = sqrtf(s2);
        float nn = fmaxf(n2, EPSF);
        float fac = tanhf(nn) / nn;
        float ny = fac * n2;
        float F = fac;
        if (ny > MAXNORM) F = fac * (MAXNORM / fmaxf(ny, EPSF));
        shF = F;
    }
    __syncthreads();
    if (c < 10) out[g * 10 + c] = shz[c] * shF;
}

// ---------------- launch ------------------------------------------------------
extern "C" void kernel_launch(void* const* d_in, const int* in_sizes, int n_in,
                              void* d_out, int out_size) {
    const float* x  = (const float*)d_in[0];
    const void*  ei = d_in[1];
    const void*  ba = d_in[2];
    const float* W1 = (const float*)d_in[3];
    const float* b1 = (const float*)d_in[4];
    const float* W2 = (const float*)d_in[5];
    const float* b2 = (const float*)d_in[6];
    const float* W3 = (const float*)d_in[7];
    const float* b3 = (const float*)d_in[8];
    const float* Wl = (const float*)d_in[9];
    const float* bl = (const float*)d_in[10];
    float* out = (float*)d_out;

    zero_kernel<<<(NN + 255) / 256, 256>>>((const int*)ei, (const int*)ba);
    deg_kernel<<<EQ_BLKS, 256>>>(ei);
    scan_kernel<<<NBLK, 1024>>>(ba);
    adj_t0_kernel<<<EQ_BLKS + T0_BLKS, 256>>>(ei, x);

    const int GEMM_GRID = (NN + 63) / 64;

    agg32_kernel<<<(NN * 16 + 255) / 256, 256>>>();
    gemm_kernel<32, 1, 0><<<GEMM_GRID, 256>>>(W1, b1, ba);
    agg64_kernel<<<(NN * 32 + 255) / 256, 256>>>();
    gemm_kernel<64, 1, 0><<<GEMM_GRID, 256>>>(W2, b2, ba);
    agg64_kernel<<<(NN * 32 + 255) / 256, 256>>>();
    gemm_kernel<64, 0, 1><<<GEMM_GRID, 256>>>(W3, b3, ba);

    final_kernel<<<NG, 64>>>(Wl, bl, out);
}